// round 1
// baseline (speedup 1.0000x reference)
#include <cuda_runtime.h>

// SeqClassLSTM: B independent LSTM(T=128, in=1, H=32) + FC(32->2).
// One warp per batch element. Lane l owns gate rows {l, l+32, l+64, l+96}
// (= gates i,f,g,o of hidden unit l), so lane l computes h[l], c[l] locally.
// W_hh lives in registers as packed f32x2 pairs; h is broadcast via shuffles.
// Inner product uses fma.rn.f32x2 (packed dual-fp32 FMA, sm_100+).

using ull = unsigned long long;

__device__ __forceinline__ ull fma2(ull a, ull b, ull c) {
    ull d;
    asm("fma.rn.f32x2 %0, %1, %2, %3;" : "=l"(d) : "l"(a), "l"(b), "l"(c));
    return d;
}
__device__ __forceinline__ ull pack2(float lo, float hi) {
    ull r;
    asm("mov.b64 %0, {%1, %2};" : "=l"(r) : "f"(lo), "f"(hi));
    return r;
}
__device__ __forceinline__ void unpack2(ull v, float& lo, float& hi) {
    asm("mov.b64 {%0, %1}, %2;" : "=f"(lo), "=f"(hi) : "l"(v));
}

// sigmoid via MUFU.EX2 + MUFU.RCP (accurate to ~1e-7 abs; tanh.approx is too coarse)
__device__ __forceinline__ float fast_sigmoid(float v) {
    float t = -1.4426950408889634f * v;   // -v * log2(e)
    float e;
    asm("ex2.approx.f32 %0, %1;" : "=f"(e) : "f"(t));  // exp(-v)
    float d = 1.0f + e;
    float r;
    asm("rcp.approx.f32 %0, %1;" : "=f"(r) : "f"(d));
    return r;
}
__device__ __forceinline__ float fast_tanh(float v) {
    return fmaf(2.0f, fast_sigmoid(2.0f * v), -1.0f);
}

constexpr int T = 128;

__global__ void __launch_bounds__(128)
lstm_seq_kernel(const float* __restrict__ x,
                const float* __restrict__ W_ih,
                const float* __restrict__ W_hh,
                const float* __restrict__ b_ih,
                const float* __restrict__ b_hh,
                const float* __restrict__ W_fc,
                const float* __restrict__ b_fc,
                float* __restrict__ out,
                int B)
{
    const int warp = (blockIdx.x * blockDim.x + threadIdx.x) >> 5;
    const int lane = threadIdx.x & 31;
    if (warp >= B) return;

    // ---- Load W_hh rows (l, l+32, l+64, l+96) as packed f32x2: 64 ull regs ----
    const ull* Wr = reinterpret_cast<const ull*>(W_hh);  // row r = Wr + r*16
    ull wi2[16], wf2[16], wg2[16], wo2[16];
#pragma unroll
    for (int j = 0; j < 16; ++j) {
        wi2[j] = Wr[(lane      ) * 16 + j];
        wf2[j] = Wr[(lane + 32 ) * 16 + j];
        wg2[j] = Wr[(lane + 64 ) * 16 + j];
        wo2[j] = Wr[(lane + 96 ) * 16 + j];
    }

    const float bi = b_ih[lane      ] + b_hh[lane      ];
    const float bf = b_ih[lane + 32 ] + b_hh[lane + 32 ];
    const float bg = b_ih[lane + 64 ] + b_hh[lane + 64 ];
    const float bo = b_ih[lane + 96 ] + b_hh[lane + 96 ];
    const float wxi = W_ih[lane      ];
    const float wxf = W_ih[lane + 32 ];
    const float wxg = W_ih[lane + 64 ];
    const float wxo = W_ih[lane + 96 ];

    // ---- Preload this sequence's x (T=128 floats, 4 per lane) ----
    const float* xb = x + (size_t)warp * T;
    float xva[4];
#pragma unroll
    for (int u = 0; u < 4; ++u) xva[u] = xb[u * 32 + lane];

    float h = 0.0f, c = 0.0f;

#pragma unroll
    for (int tb = 0; tb < 4; ++tb) {
        const float xvb = xva[tb];
#pragma unroll 1
        for (int tt = 0; tt < 32; ++tt) {
            const float xt = __shfl_sync(0xffffffffu, xvb, tt);

            ull ai = 0ull, af = 0ull, ag = 0ull, ao = 0ull;
#pragma unroll
            for (int j = 0; j < 16; ++j) {
                const float ha = __shfl_sync(0xffffffffu, h, 2 * j);
                const float hb = __shfl_sync(0xffffffffu, h, 2 * j + 1);
                const ull h2 = pack2(ha, hb);
                ai = fma2(wi2[j], h2, ai);
                af = fma2(wf2[j], h2, af);
                ag = fma2(wg2[j], h2, ag);
                ao = fma2(wo2[j], h2, ao);
            }
            float lo, hi;
            unpack2(ai, lo, hi); const float gi = lo + hi + fmaf(wxi, xt, bi);
            unpack2(af, lo, hi); const float gf = lo + hi + fmaf(wxf, xt, bf);
            unpack2(ag, lo, hi); const float gg = lo + hi + fmaf(wxg, xt, bg);
            unpack2(ao, lo, hi); const float go = lo + hi + fmaf(wxo, xt, bo);

            const float si = fast_sigmoid(gi);
            const float sf = fast_sigmoid(gf);
            const float tg = fast_tanh(gg);
            const float so = fast_sigmoid(go);

            c = fmaf(sf, c, si * tg);
            h = so * fast_tanh(c);
        }
    }

    // ---- FC: out[b, :] = h @ W_fc.T + b_fc  (warp reduction) ----
    float v0 = h * W_fc[lane];
    float v1 = h * W_fc[32 + lane];
#pragma unroll
    for (int off = 16; off; off >>= 1) {
        v0 += __shfl_xor_sync(0xffffffffu, v0, off);
        v1 += __shfl_xor_sync(0xffffffffu, v1, off);
    }
    if (lane == 0) {
        out[(size_t)warp * 2 + 0] = v0 + b_fc[0];
        out[(size_t)warp * 2 + 1] = v1 + b_fc[1];
    }
}

extern "C" void kernel_launch(void* const* d_in, const int* in_sizes, int n_in,
                              void* d_out, int out_size)
{
    const float* x    = (const float*)d_in[0];
    const float* W_ih = (const float*)d_in[1];
    const float* W_hh = (const float*)d_in[2];
    const float* b_ih = (const float*)d_in[3];
    const float* b_hh = (const float*)d_in[4];
    const float* W_fc = (const float*)d_in[5];
    const float* b_fc = (const float*)d_in[6];
    float* out = (float*)d_out;

    const int B = in_sizes[0] / T;            // x has B*T elements
    const int warpsPerBlock = 128 / 32;       // 4
    const int blocks = (B + warpsPerBlock - 1) / warpsPerBlock;

    lstm_seq_kernel<<<blocks, 128>>>(x, W_ih, W_hh, b_ih, b_hh, W_fc, b_fc, out, B);
}

// round 2
// speedup vs baseline: 1.0449x; 1.0449x over previous
#include <cuda_runtime.h>

// SeqClassLSTM: B independent LSTM(T=128, in=1, H=32) + FC(32->2).
// One warp per batch element. Lane l owns gate rows {l, l+32, l+64, l+96},
// so lane l computes h[l], c[l] locally. W_hh lives in registers as packed
// f32x2 pairs. h is broadcast each step via shared memory: 1 STS.32 +
// __syncwarp + 8 LDS.128 broadcast loads (replaces 32 SHFLs, which were the
// R1 bottleneck: L1/MIO at 55% while fma pipe idled at 50%).

using ull = unsigned long long;

__device__ __forceinline__ ull fma2(ull a, ull b, ull c) {
    ull d;
    asm("fma.rn.f32x2 %0, %1, %2, %3;" : "=l"(d) : "l"(a), "l"(b), "l"(c));
    return d;
}
__device__ __forceinline__ void unpack2(ull v, float& lo, float& hi) {
    asm("mov.b64 {%0, %1}, %2;" : "=f"(lo), "=f"(hi) : "l"(v));
}

// sigmoid via MUFU.EX2 + MUFU.RCP (accurate; tanh.approx too coarse for 1e-3)
__device__ __forceinline__ float fast_sigmoid(float v) {
    float t = -1.4426950408889634f * v;
    float e;
    asm("ex2.approx.f32 %0, %1;" : "=f"(e) : "f"(t));
    float d = 1.0f + e;
    float r;
    asm("rcp.approx.f32 %0, %1;" : "=f"(r) : "f"(d));
    return r;
}
__device__ __forceinline__ float fast_tanh(float v) {
    return fmaf(2.0f, fast_sigmoid(2.0f * v), -1.0f);
}

constexpr int T = 128;
constexpr int WARPS_PER_BLOCK = 4;

__global__ void __launch_bounds__(128)
lstm_seq_kernel(const float* __restrict__ x,
                const float* __restrict__ W_ih,
                const float* __restrict__ W_hh,
                const float* __restrict__ b_ih,
                const float* __restrict__ b_hh,
                const float* __restrict__ W_fc,
                const float* __restrict__ b_fc,
                float* __restrict__ out,
                int B)
{
    __shared__ float hbuf[2][WARPS_PER_BLOCK][32];

    const int wblk = threadIdx.x >> 5;
    const int warp = blockIdx.x * WARPS_PER_BLOCK + wblk;
    const int lane = threadIdx.x & 31;
    if (warp >= B) return;

    // ---- W_hh rows (l, l+32, l+64, l+96) as packed f32x2: 64 ull regs ----
    const ull* Wr = reinterpret_cast<const ull*>(W_hh);  // row r = Wr + r*16
    ull wi2[16], wf2[16], wg2[16], wo2[16];
#pragma unroll
    for (int j = 0; j < 16; ++j) {
        wi2[j] = Wr[(lane      ) * 16 + j];
        wf2[j] = Wr[(lane + 32 ) * 16 + j];
        wg2[j] = Wr[(lane + 64 ) * 16 + j];
        wo2[j] = Wr[(lane + 96 ) * 16 + j];
    }

    const float bi = b_ih[lane      ] + b_hh[lane      ];
    const float bf = b_ih[lane + 32 ] + b_hh[lane + 32 ];
    const float bg = b_ih[lane + 64 ] + b_hh[lane + 64 ];
    const float bo = b_ih[lane + 96 ] + b_hh[lane + 96 ];
    const float wxi = W_ih[lane      ];
    const float wxf = W_ih[lane + 32 ];
    const float wxg = W_ih[lane + 64 ];
    const float wxo = W_ih[lane + 96 ];

    // ---- Preload this sequence's x (T=128 floats, 4 per lane) ----
    const float* xb = x + (size_t)warp * T;
    float xva[4];
#pragma unroll
    for (int u = 0; u < 4; ++u) xva[u] = xb[u * 32 + lane];

    float* const hb0 = &hbuf[0][wblk][0];
    float* const hb1 = &hbuf[1][wblk][0];

    float h = 0.0f, c = 0.0f;

#pragma unroll
    for (int tb = 0; tb < 4; ++tb) {
        const float xvb = xva[tb];
#pragma unroll 2
        for (int tt = 0; tt < 32; ++tt) {
            const float xt = __shfl_sync(0xffffffffu, xvb, tt);
            float* const hb = (tt & 1) ? hb1 : hb0;

            hb[lane] = h;
            __syncwarp();

            // Broadcast read of the whole h vector: 8x LDS.128, all lanes
            // same address (conflict-free broadcast).
            union { float4 f4[8]; ull u2[16]; } H;
            const float4* hp = reinterpret_cast<const float4*>(hb);
#pragma unroll
            for (int q = 0; q < 8; ++q) H.f4[q] = hp[q];

            ull ai = 0ull, af = 0ull, ag = 0ull, ao = 0ull;
#pragma unroll
            for (int j = 0; j < 16; ++j) {
                const ull h2 = H.u2[j];
                ai = fma2(wi2[j], h2, ai);
                af = fma2(wf2[j], h2, af);
                ag = fma2(wg2[j], h2, ag);
                ao = fma2(wo2[j], h2, ao);
            }
            float lo, hi;
            unpack2(ai, lo, hi); const float gi = (lo + hi) + fmaf(wxi, xt, bi);
            unpack2(af, lo, hi); const float gf = (lo + hi) + fmaf(wxf, xt, bf);
            unpack2(ag, lo, hi); const float gg = (lo + hi) + fmaf(wxg, xt, bg);
            unpack2(ao, lo, hi); const float go = (lo + hi) + fmaf(wxo, xt, bo);

            const float si = fast_sigmoid(gi);
            const float sf = fast_sigmoid(gf);
            const float tg = fast_tanh(gg);
            const float so = fast_sigmoid(go);

            c = fmaf(sf, c, si * tg);
            h = so * fast_tanh(c);
        }
    }

    // ---- FC: out[b, :] = h @ W_fc.T + b_fc  (warp reduction) ----
    float v0 = h * W_fc[lane];
    float v1 = h * W_fc[32 + lane];
#pragma unroll
    for (int off = 16; off; off >>= 1) {
        v0 += __shfl_xor_sync(0xffffffffu, v0, off);
        v1 += __shfl_xor_sync(0xffffffffu, v1, off);
    }
    if (lane == 0) {
        out[(size_t)warp * 2 + 0] = v0 + b_fc[0];
        out[(size_t)warp * 2 + 1] = v1 + b_fc[1];
    }
}

extern "C" void kernel_launch(void* const* d_in, const int* in_sizes, int n_in,
                              void* d_out, int out_size)
{
    const float* x    = (const float*)d_in[0];
    const float* W_ih = (const float*)d_in[1];
    const float* W_hh = (const float*)d_in[2];
    const float* b_ih = (const float*)d_in[3];
    const float* b_hh = (const float*)d_in[4];
    const float* W_fc = (const float*)d_in[5];
    const float* b_fc = (const float*)d_in[6];
    float* out = (float*)d_out;

    const int B = in_sizes[0] / T;  // x has B*T elements
    const int blocks = (B + WARPS_PER_BLOCK - 1) / WARPS_PER_BLOCK;

    lstm_seq_kernel<<<blocks, 128>>>(x, W_ih, W_hh, b_ih, b_hh, W_fc, b_fc, out, B);
}

// round 3
// speedup vs baseline: 1.1386x; 1.0896x over previous
#include <cuda_runtime.h>

// SeqClassLSTM: B independent LSTM(T=128, in=1, H=32) + FC(32->2).
// TWO sequences per warp: the 128 weight registers (W_hh as packed f32x2)
// are amortized over 2 batch elements, giving 128 FFMA2/step in 8 independent
// chains per warp. R2 showed the kernel was latency-bound (occ 18.6%, issue
// 45%, fma 52%): not enough independent FMA work per SMSP. This doubles FMA
// density per warp at ~+30 regs.
// Lane l owns gate rows {l, l+32, l+64, l+96} -> computes h[l], c[l] locally.
// h broadcast via smem double-buffer: 1 STS + syncwarp + LDS.128 broadcasts.

using ull = unsigned long long;

__device__ __forceinline__ ull fma2(ull a, ull b, ull c) {
    ull d;
    asm("fma.rn.f32x2 %0, %1, %2, %3;" : "=l"(d) : "l"(a), "l"(b), "l"(c));
    return d;
}
__device__ __forceinline__ ull pack2(float lo, float hi) {
    ull r;
    asm("mov.b64 %0, {%1, %2};" : "=l"(r) : "f"(lo), "f"(hi));
    return r;
}
__device__ __forceinline__ void unpack2(ull v, float& lo, float& hi) {
    asm("mov.b64 {%0, %1}, %2;" : "=f"(lo), "=f"(hi) : "l"(v));
}

// sigmoid via MUFU.EX2 + MUFU.RCP (accurate; tanh.approx too coarse for 1e-3)
__device__ __forceinline__ float fast_sigmoid(float v) {
    float t = -1.4426950408889634f * v;
    float e;
    asm("ex2.approx.f32 %0, %1;" : "=f"(e) : "f"(t));
    float d = 1.0f + e;
    float r;
    asm("rcp.approx.f32 %0, %1;" : "=f"(r) : "f"(d));
    return r;
}
__device__ __forceinline__ float fast_tanh(float v) {
    return fmaf(2.0f, fast_sigmoid(2.0f * v), -1.0f);
}

constexpr int T = 128;
constexpr int WPB = 4;   // warps per block

__global__ void __launch_bounds__(128, 2)
lstm_seq_kernel(const float* __restrict__ x,
                const float* __restrict__ W_ih,
                const float* __restrict__ W_hh,
                const float* __restrict__ b_ih,
                const float* __restrict__ b_hh,
                const float* __restrict__ W_fc,
                const float* __restrict__ b_fc,
                float* __restrict__ out,
                int B)
{
    __shared__ __align__(16) float hbuf[2][2][WPB][32];  // [buf][seq][warp][lane]

    const int wblk = threadIdx.x >> 5;
    const int lane = threadIdx.x & 31;
    const int pair = blockIdx.x * WPB + wblk;
    const int b0 = pair * 2;
    const int b1 = b0 + 1;
    if (b0 >= B) return;

    // ---- W_hh rows (l, l+32, l+64, l+96) as packed f32x2: 64 ull regs ----
    const ull* Wr = reinterpret_cast<const ull*>(W_hh);  // row r = Wr + r*16
    ull wi2[16], wf2[16], wg2[16], wo2[16];
#pragma unroll
    for (int j = 0; j < 16; ++j) {
        wi2[j] = Wr[(lane      ) * 16 + j];
        wf2[j] = Wr[(lane + 32 ) * 16 + j];
        wg2[j] = Wr[(lane + 64 ) * 16 + j];
        wo2[j] = Wr[(lane + 96 ) * 16 + j];
    }

    const float bi = b_ih[lane      ] + b_hh[lane      ];
    const float bf = b_ih[lane + 32 ] + b_hh[lane + 32 ];
    const float bg = b_ih[lane + 64 ] + b_hh[lane + 64 ];
    const float bo = b_ih[lane + 96 ] + b_hh[lane + 96 ];
    const float wxi = W_ih[lane      ];
    const float wxf = W_ih[lane + 32 ];
    const float wxg = W_ih[lane + 64 ];
    const float wxo = W_ih[lane + 96 ];

    // ---- Preload both sequences' x (T=128 floats, 4 per lane each) ----
    const float* xp0 = x + (size_t)b0 * T;
    const float* xp1 = x + (size_t)b1 * T;
    float xvA[4], xvB[4];
#pragma unroll
    for (int u = 0; u < 4; ++u) { xvA[u] = xp0[u * 32 + lane]; xvB[u] = xp1[u * 32 + lane]; }

    float hA = 0.0f, cA = 0.0f, hB = 0.0f, cB = 0.0f;

#pragma unroll
    for (int tb = 0; tb < 4; ++tb) {
        const float xa = xvA[tb];
        const float xb = xvB[tb];
#pragma unroll 2
        for (int tt = 0; tt < 32; ++tt) {
            const float xtA = __shfl_sync(0xffffffffu, xa, tt);
            const float xtB = __shfl_sync(0xffffffffu, xb, tt);

            float* const sA = &hbuf[tt & 1][0][wblk][0];
            float* const sB = &hbuf[tt & 1][1][wblk][0];
            sA[lane] = hA;
            sB[lane] = hB;
            __syncwarp();

            // Fold x-term + bias into accumulator init (saves post-adds)
            ull aiA = pack2(fmaf(wxi, xtA, bi), 0.0f);
            ull afA = pack2(fmaf(wxf, xtA, bf), 0.0f);
            ull agA = pack2(fmaf(wxg, xtA, bg), 0.0f);
            ull aoA = pack2(fmaf(wxo, xtA, bo), 0.0f);
            ull aiB = pack2(fmaf(wxi, xtB, bi), 0.0f);
            ull afB = pack2(fmaf(wxf, xtB, bf), 0.0f);
            ull agB = pack2(fmaf(wxg, xtB, bg), 0.0f);
            ull aoB = pack2(fmaf(wxo, xtB, bo), 0.0f);

            const ulonglong2* pA = reinterpret_cast<const ulonglong2*>(sA);
            const ulonglong2* pB = reinterpret_cast<const ulonglong2*>(sB);
#pragma unroll
            for (int q = 0; q < 8; ++q) {
                const ulonglong2 HA = pA[q];   // LDS.128 broadcast (all lanes same addr)
                const ulonglong2 HB = pB[q];
                aiA = fma2(wi2[2*q  ], HA.x, aiA);
                afA = fma2(wf2[2*q  ], HA.x, afA);
                agA = fma2(wg2[2*q  ], HA.x, agA);
                aoA = fma2(wo2[2*q  ], HA.x, aoA);
                aiA = fma2(wi2[2*q+1], HA.y, aiA);
                afA = fma2(wf2[2*q+1], HA.y, afA);
                agA = fma2(wg2[2*q+1], HA.y, agA);
                aoA = fma2(wo2[2*q+1], HA.y, aoA);
                aiB = fma2(wi2[2*q  ], HB.x, aiB);
                afB = fma2(wf2[2*q  ], HB.x, afB);
                agB = fma2(wg2[2*q  ], HB.x, agB);
                aoB = fma2(wo2[2*q  ], HB.x, aoB);
                aiB = fma2(wi2[2*q+1], HB.y, aiB);
                afB = fma2(wf2[2*q+1], HB.y, afB);
                agB = fma2(wg2[2*q+1], HB.y, agB);
                aoB = fma2(wo2[2*q+1], HB.y, aoB);
            }

            float lo, hi;
            unpack2(aiA, lo, hi); const float giA = lo + hi;
            unpack2(afA, lo, hi); const float gfA = lo + hi;
            unpack2(agA, lo, hi); const float ggA = lo + hi;
            unpack2(aoA, lo, hi); const float goA = lo + hi;
            unpack2(aiB, lo, hi); const float giB = lo + hi;
            unpack2(afB, lo, hi); const float gfB = lo + hi;
            unpack2(agB, lo, hi); const float ggB = lo + hi;
            unpack2(aoB, lo, hi); const float goB = lo + hi;

            const float siA = fast_sigmoid(giA);
            const float siB = fast_sigmoid(giB);
            const float sfA = fast_sigmoid(gfA);
            const float sfB = fast_sigmoid(gfB);
            const float tgA = fast_tanh(ggA);
            const float tgB = fast_tanh(ggB);
            const float soA = fast_sigmoid(goA);
            const float soB = fast_sigmoid(goB);

            cA = fmaf(sfA, cA, siA * tgA);
            cB = fmaf(sfB, cB, siB * tgB);
            hA = soA * fast_tanh(cA);
            hB = soB * fast_tanh(cB);
        }
    }

    // ---- FC: out[b, :] = h @ W_fc.T + b_fc  (warp reductions) ----
    const float w0 = W_fc[lane];
    const float w1 = W_fc[32 + lane];
    float v0A = hA * w0, v1A = hA * w1;
    float v0B = hB * w0, v1B = hB * w1;
#pragma unroll
    for (int off = 16; off; off >>= 1) {
        v0A += __shfl_xor_sync(0xffffffffu, v0A, off);
        v1A += __shfl_xor_sync(0xffffffffu, v1A, off);
        v0B += __shfl_xor_sync(0xffffffffu, v0B, off);
        v1B += __shfl_xor_sync(0xffffffffu, v1B, off);
    }
    if (lane == 0) {
        out[(size_t)b0 * 2 + 0] = v0A + b_fc[0];
        out[(size_t)b0 * 2 + 1] = v1A + b_fc[1];
        out[(size_t)b1 * 2 + 0] = v0B + b_fc[0];
        out[(size_t)b1 * 2 + 1] = v1B + b_fc[1];
    }
}

extern "C" void kernel_launch(void* const* d_in, const int* in_sizes, int n_in,
                              void* d_out, int out_size)
{
    const float* x    = (const float*)d_in[0];
    const float* W_ih = (const float*)d_in[1];
    const float* W_hh = (const float*)d_in[2];
    const float* b_ih = (const float*)d_in[3];
    const float* b_hh = (const float*)d_in[4];
    const float* W_fc = (const float*)d_in[5];
    const float* b_fc = (const float*)d_in[6];
    float* out = (float*)d_out;

    const int B = in_sizes[0] / T;               // x has B*T elements
    const int pairs = (B + 1) / 2;               // 2 sequences per warp
    const int blocks = (pairs + WPB - 1) / WPB;

    lstm_seq_kernel<<<blocks, 128>>>(x, W_ih, W_hh, b_ih, b_hh, W_fc, b_fc, out, B);
}

// round 4
// speedup vs baseline: 1.5275x; 1.3416x over previous
#include <cuda_runtime.h>

// SeqClassLSTM: B independent LSTM(T=128, in=1, H=32) + FC(32->2).
// THREE sequences per warp: 128 weight regs (W_hh as packed f32x2) amortized
// over 3 batch elements -> 24 independent FMA chains per step. Activations via
// MUFU.TANH (tanh.approx.f32): halves the chip-wide MUFU floor (was ~1.2ms
// with ex2+rcp sigmoids, >25% of R3's runtime).
// Lane l owns gate rows {l, l+32, l+64, l+96} -> computes h[l], c[l] locally.
// h broadcast via smem double-buffer: STS + syncwarp + LDS.128 broadcasts.

using ull = unsigned long long;

__device__ __forceinline__ ull fma2(ull a, ull b, ull c) {
    ull d;
    asm("fma.rn.f32x2 %0, %1, %2, %3;" : "=l"(d) : "l"(a), "l"(b), "l"(c));
    return d;
}
__device__ __forceinline__ ull pack2(float lo, float hi) {
    ull r;
    asm("mov.b64 %0, {%1, %2};" : "=l"(r) : "f"(lo), "f"(hi));
    return r;
}
__device__ __forceinline__ void unpack2(ull v, float& lo, float& hi) {
    asm("mov.b64 {%0, %1}, %2;" : "=f"(lo), "=f"(hi) : "l"(v));
}
__device__ __forceinline__ float tanh_a(float v) {
    float r;
    asm("tanh.approx.f32 %0, %1;" : "=f"(r) : "f"(v));
    return r;
}
__device__ __forceinline__ float sigmoid_a(float v) {
    return fmaf(0.5f, tanh_a(0.5f * v), 0.5f);
}

constexpr int T = 128;
constexpr int S = 3;     // sequences per warp
constexpr int WPB = 4;   // warps per block

__global__ void __launch_bounds__(128, 2)
lstm_seq_kernel(const float* __restrict__ x,
                const float* __restrict__ W_ih,
                const float* __restrict__ W_hh,
                const float* __restrict__ b_ih,
                const float* __restrict__ b_hh,
                const float* __restrict__ W_fc,
                const float* __restrict__ b_fc,
                float* __restrict__ out,
                int B)
{
    __shared__ __align__(16) float hbuf[2][WPB][S][32];  // [buf][warp][seq][lane]

    const int wblk = threadIdx.x >> 5;
    const int lane = threadIdx.x & 31;
    const int base = (blockIdx.x * WPB + wblk) * S;
    if (base >= B) return;

    // ---- W_hh rows (l, l+32, l+64, l+96) as packed f32x2: 64 ull (128 regs) ----
    const ull* Wr = reinterpret_cast<const ull*>(W_hh);  // row r = Wr + r*16
    ull wi2[16], wf2[16], wg2[16], wo2[16];
#pragma unroll
    for (int j = 0; j < 16; ++j) {
        wi2[j] = Wr[(lane      ) * 16 + j];
        wf2[j] = Wr[(lane + 32 ) * 16 + j];
        wg2[j] = Wr[(lane + 64 ) * 16 + j];
        wo2[j] = Wr[(lane + 96 ) * 16 + j];
    }

    // Pre-packed biases: first fma2 of each chain uses these as c-operand.
    const ull BI = pack2(b_ih[lane      ] + b_hh[lane      ], 0.0f);
    const ull BF = pack2(b_ih[lane + 32 ] + b_hh[lane + 32 ], 0.0f);
    const ull BG = pack2(b_ih[lane + 64 ] + b_hh[lane + 64 ], 0.0f);
    const ull BO = pack2(b_ih[lane + 96 ] + b_hh[lane + 96 ], 0.0f);
    const float wxi = W_ih[lane      ];
    const float wxf = W_ih[lane + 32 ];
    const float wxg = W_ih[lane + 64 ];
    const float wxo = W_ih[lane + 96 ];

    // ---- Preload x for all S sequences (4 floats per lane each) ----
    float xv[S][4];
#pragma unroll
    for (int s = 0; s < S; ++s) {
        const int bs = base + s;
        const float* xp = x + (size_t)bs * T;
#pragma unroll
        for (int u = 0; u < 4; ++u)
            xv[s][u] = (bs < B) ? xp[u * 32 + lane] : 0.0f;
    }

    float h[S], c[S];
#pragma unroll
    for (int s = 0; s < S; ++s) { h[s] = 0.0f; c[s] = 0.0f; }

#pragma unroll
    for (int tb = 0; tb < 4; ++tb) {
#pragma unroll 1
        for (int tt = 0; tt < 32; ++tt) {
            float xt[S];
#pragma unroll
            for (int s = 0; s < S; ++s)
                xt[s] = __shfl_sync(0xffffffffu, xv[s][tb], tt);

#pragma unroll
            for (int s = 0; s < S; ++s)
                hbuf[tt & 1][wblk][s][lane] = h[s];
            __syncwarp();

            ull ai[S], af[S], ag[S], ao[S];
#pragma unroll
            for (int q = 0; q < 8; ++q) {
#pragma unroll
                for (int s = 0; s < S; ++s) {
                    // LDS.128 broadcast: all lanes read same address
                    const ulonglong2 H = reinterpret_cast<const ulonglong2*>(
                        &hbuf[tt & 1][wblk][s][0])[q];
                    if (q == 0) {
                        ai[s] = fma2(wi2[0], H.x, BI);
                        af[s] = fma2(wf2[0], H.x, BF);
                        ag[s] = fma2(wg2[0], H.x, BG);
                        ao[s] = fma2(wo2[0], H.x, BO);
                    } else {
                        ai[s] = fma2(wi2[2*q], H.x, ai[s]);
                        af[s] = fma2(wf2[2*q], H.x, af[s]);
                        ag[s] = fma2(wg2[2*q], H.x, ag[s]);
                        ao[s] = fma2(wo2[2*q], H.x, ao[s]);
                    }
                    ai[s] = fma2(wi2[2*q+1], H.y, ai[s]);
                    af[s] = fma2(wf2[2*q+1], H.y, af[s]);
                    ag[s] = fma2(wg2[2*q+1], H.y, ag[s]);
                    ao[s] = fma2(wo2[2*q+1], H.y, ao[s]);
                }
            }

#pragma unroll
            for (int s = 0; s < S; ++s) {
                float lo, hi;
                unpack2(ai[s], lo, hi); const float gi = fmaf(wxi, xt[s], lo + hi);
                unpack2(af[s], lo, hi); const float gf = fmaf(wxf, xt[s], lo + hi);
                unpack2(ag[s], lo, hi); const float gg = fmaf(wxg, xt[s], lo + hi);
                unpack2(ao[s], lo, hi); const float go = fmaf(wxo, xt[s], lo + hi);

                const float si = sigmoid_a(gi);
                const float sf = sigmoid_a(gf);
                const float tg = tanh_a(gg);
                const float so = sigmoid_a(go);

                c[s] = fmaf(sf, c[s], si * tg);
                h[s] = so * tanh_a(c[s]);
            }
        }
    }

    // ---- FC: out[b, :] = h @ W_fc.T + b_fc  (warp reductions) ----
    const float w0 = W_fc[lane];
    const float w1 = W_fc[32 + lane];
#pragma unroll
    for (int s = 0; s < S; ++s) {
        float v0 = h[s] * w0;
        float v1 = h[s] * w1;
#pragma unroll
        for (int off = 16; off; off >>= 1) {
            v0 += __shfl_xor_sync(0xffffffffu, v0, off);
            v1 += __shfl_xor_sync(0xffffffffu, v1, off);
        }
        const int bs = base + s;
        if (lane == 0 && bs < B) {
            out[(size_t)bs * 2 + 0] = v0 + b_fc[0];
            out[(size_t)bs * 2 + 1] = v1 + b_fc[1];
        }
    }
}

extern "C" void kernel_launch(void* const* d_in, const int* in_sizes, int n_in,
                              void* d_out, int out_size)
{
    const float* x    = (const float*)d_in[0];
    const float* W_ih = (const float*)d_in[1];
    const float* W_hh = (const float*)d_in[2];
    const float* b_ih = (const float*)d_in[3];
    const float* b_hh = (const float*)d_in[4];
    const float* W_fc = (const float*)d_in[5];
    const float* b_fc = (const float*)d_in[6];
    float* out = (float*)d_out;

    const int B = in_sizes[0] / T;                   // x has B*T elements
    const int groups = (B + S - 1) / S;              // S sequences per warp
    const int blocks = (groups + WPB - 1) / WPB;

    lstm_seq_kernel<<<blocks, 128>>>(x, W_ih, W_hh, b_ih, b_hh, W_fc, b_fc, out, B);
}